// round 15
// baseline (speedup 1.0000x reference)
#include <cuda_runtime.h>
#include <cuda_bf16.h>
#include <cuda_fp16.h>
#include <cuda_fp8.h>
#include <cstdint>
#include <cstddef>

// ---------------- problem constants ----------------------------------------
#define BATCH 16
#define NLOG  512
#define Q     2048
#define EDG   2048
#define MROWS (BATCH * NLOG)   // 8192

// ---------------- FP8 GEMM tiling -------------------------------------------
#define BM 128
#define BN 128
#define BK 128                // e4m3 elements per chunk (128 bytes/row)
#define NKT (Q / BK)          // 16
#define LDR 144               // row stride bytes: 128 + 16 pad (conflict-free ldsm)
#define A_BYTES (BM * LDR)                 // 18432
#define STAGE_BYTES (2 * A_BYTES)          // 36864 (A + B)
#define NSTAGE 3
#define SMEM_SZ (NSTAGE * STAGE_BYTES)     // 110592 B -> 2 CTAs/SM

// ---------------- scratch (device globals; no allocation allowed) ----------
__device__ __nv_bfloat16 g_Pb[(size_t)MROWS * Q];   // P bf16 (32 MB, stage2)
__device__ uint8_t       g_P8[(size_t)MROWS * Q];   // P e4m3 (16 MB, GEMM A)
__device__ uint8_t       g_B8[(size_t)Q * Q];       // A_hw^T e4m3 [n][k] (4 MB, GEMM B)
__device__ __nv_bfloat16 g_PA[(size_t)MROWS * Q];   // P @ A_hw bf16 (32 MB)
__device__ float g_edot[BATCH * EDG];
__device__ float g_num[BATCH];
__device__ float g_den[BATCH];

// ---------------- PTX helpers ----------------------------------------------
__device__ __forceinline__ void cp16s(uint32_t s, const void* g) {
    asm volatile("cp.async.cg.shared.global [%0], [%1], 16;\n" :: "r"(s), "l"(g));
}
__device__ __forceinline__ void cp_commit() {
    asm volatile("cp.async.commit_group;\n" ::);
}
__device__ __forceinline__ void cp_wait1() {
    asm volatile("cp.async.wait_group 1;\n" ::);
}
__device__ __forceinline__ void cp_wait0() {
    asm volatile("cp.async.wait_group 0;\n" ::);
}
__device__ __forceinline__ void ldsm4(uint32_t& r0, uint32_t& r1, uint32_t& r2, uint32_t& r3,
                                      uint32_t a) {
    asm volatile("ldmatrix.sync.aligned.m8n8.x4.shared.b16 {%0,%1,%2,%3}, [%4];"
                 : "=r"(r0), "=r"(r1), "=r"(r2), "=r"(r3) : "r"(a));
}
// m16n8k32 e4m3 x e4m3 -> f16 accumulate (C/D = 2 x f16x2 regs)
__device__ __forceinline__ void qmma16(uint32_t* c, const uint32_t* a,
                                       uint32_t b0, uint32_t b1) {
    asm volatile(
        "mma.sync.aligned.m16n8k32.row.col.f16.e4m3.e4m3.f16 "
        "{%0,%1}, {%2,%3,%4,%5}, {%6,%7}, {%0,%1};"
        : "+r"(c[0]), "+r"(c[1])
        : "r"(a[0]), "r"(a[1]), "r"(a[2]), "r"(a[3]), "r"(b0), "r"(b1));
}

// ---------------- kernel 1: P fp32 -> bf16 + e4m3 ---------------------------
__global__ void conv_p_kernel(const float* __restrict__ P) {
    int i = blockIdx.x * blockDim.x + threadIdx.x;     // 4 floats each
    float4 v = reinterpret_cast<const float4*>(P)[i];
    __nv_bfloat162* ob = reinterpret_cast<__nv_bfloat162*>(g_Pb);
    ob[2 * i + 0] = __floats2bfloat162_rn(v.x, v.y);
    ob[2 * i + 1] = __floats2bfloat162_rn(v.z, v.w);
    __nv_fp8x2_e4m3 lo(float2{v.x, v.y});   // low byte = v.x
    __nv_fp8x2_e4m3 hi(float2{v.z, v.w});
    uint32_t packed = (uint32_t)lo.__x | ((uint32_t)hi.__x << 16);
    reinterpret_cast<uint32_t*>(g_P8)[i] = packed;
}

// ---------------- kernel 2: g_B8[n][k] = (d_hw[k][n]==1) as e4m3, transpose -
__global__ void build_at_kernel(const int* __restrict__ dhw) {
    __shared__ uint8_t t[32][33];
    const int n0 = blockIdx.x * 32;
    const int k0 = blockIdx.y * 32;
    const int tx = threadIdx.x;       // 0..31
    const int ty = threadIdx.y;       // 0..7
#pragma unroll
    for (int j = 0; j < 4; j++) {
        int k = k0 + ty + j * 8;
        int d = dhw[(size_t)k * Q + n0 + tx];
        t[ty + j * 8][tx] = (d == 1) ? 0x38 : 0x00;   // e4m3 1.0 / 0.0
    }
    __syncthreads();
#pragma unroll
    for (int j = 0; j < 4; j++) {
        int n = n0 + ty + j * 8;
        g_B8[(size_t)n * Q + k0 + tx] = t[tx][ty + j * 8];
    }
}

// ---------------- kernel 2.5: tiny init (keeps GEMM in ncu slot 4) ----------
__global__ void init_kernel() {
    if (threadIdx.x < BATCH) { g_num[threadIdx.x] = 0.f; g_den[threadIdx.x] = 0.f; }
}

// ---------------- kernel 3: PA = P8 @ B8^T, FP8 mma.sync, f16 acc -----------
// 256 threads, warptile 32x64, 3-stage ring, occupancy 2, and register-level
// fragment double-buffering: ldsm for ks+1 issues before the qmma of ks.
__global__ __launch_bounds__(256, 2) void gemm_fp8_kernel() {
    extern __shared__ uint8_t smem[];

    const int m0 = blockIdx.y * BM;
    const int n0 = blockIdx.x * BN;
    const int tid = threadIdx.x;
    const int lane = tid & 31;
    const int warp = tid >> 5;
    const int wm = warp & 3;   // warptile 32 along M
    const int wn = warp >> 2;  // warptile 64 along N

    const uint32_t smem_base = (uint32_t)__cvta_generic_to_shared(smem);

    // --- producer addressing (per-thread, hoisted) ---
    const int prow = tid >> 3;                 // 0..31
    const int pcol = (tid & 7) * 16;
    const uint8_t* gA = g_P8 + (size_t)(m0 + prow) * Q + pcol;
    const uint8_t* gB = g_B8 + (size_t)(n0 + prow) * Q + pcol;
    const uint32_t soff = (uint32_t)(prow * LDR + pcol);

    // --- consumer addressing (per-thread, hoisted) ---
    const uint32_t aoff = (uint32_t)((wm * 32 + (lane & 15)) * LDR + (lane >> 4) * 16);
    const uint32_t boff = (uint32_t)A_BYTES +
        (uint32_t)((wn * 64 + ((lane >> 4) << 3) + (lane & 7)) * LDR +
                   ((lane >> 3) & 1) * 16);

    uint32_t acc[2][8][2];   // f16x2 accumulators, 32 regs
#pragma unroll
    for (int mt = 0; mt < 2; mt++)
#pragma unroll
        for (int nt = 0; nt < 8; nt++) { acc[mt][nt][0] = 0u; acc[mt][nt][1] = 0u; }

    // one stage fill: A 4 slots + B 4 slots per thread, immediates only
    auto fill = [&](uint32_t sb) {
#pragma unroll
        for (int i = 0; i < 4; i++) {
            cp16s(sb + soff + (uint32_t)(i * 32 * LDR), gA + (size_t)i * 32 * Q);
            cp16s(sb + soff + (uint32_t)(i * 32 * LDR) + A_BYTES, gB + (size_t)i * 32 * Q);
        }
        cp_commit();
        gA += BK; gB += BK;
    };

    // double-buffered fragments (48 regs)
    uint32_t a[2][2][4];   // [buf][mt][4]
    uint32_t b[2][8][2];   // [buf][nt][2]

    auto ld_frags = [&](int buf, uint32_t Ab, uint32_t Bb, int ks) {
#pragma unroll
        for (int mt = 0; mt < 2; mt++)
            ldsm4(a[buf][mt][0], a[buf][mt][1], a[buf][mt][2], a[buf][mt][3],
                  Ab + (uint32_t)(mt * 16 * LDR + ks * 32));
#pragma unroll
        for (int nt2 = 0; nt2 < 4; nt2++)
            ldsm4(b[buf][2 * nt2][0], b[buf][2 * nt2][1],
                  b[buf][2 * nt2 + 1][0], b[buf][2 * nt2 + 1][1],
                  Bb + (uint32_t)(nt2 * 16 * LDR + ks * 32));
    };

    // prologue: stages 0,1
    fill(smem_base);
    fill(smem_base + STAGE_BYTES);

    int s = 0, ps = 2;   // compute stage, prefetch stage
    for (int kt = 0; kt < NKT; kt++) {
        if (kt + 1 < NKT) cp_wait1(); else cp_wait0();
        __syncthreads();

        // prefetch first: slot ps was freed at the barrier above
        if (kt + 2 < NKT)
            fill(smem_base + (uint32_t)ps * STAGE_BYTES);

        const uint32_t Ab = smem_base + (uint32_t)s * STAGE_BYTES + aoff;
        const uint32_t Bb = smem_base + (uint32_t)s * STAGE_BYTES + boff;

        ld_frags(0, Ab, Bb, 0);
#pragma unroll
        for (int ks = 0; ks < 4; ks++) {           // four k32 steps per BK=128
            const int cb = ks & 1;
            if (ks < 3) ld_frags(cb ^ 1, Ab, Bb, ks + 1);
#pragma unroll
            for (int mt = 0; mt < 2; mt++)
#pragma unroll
                for (int nt = 0; nt < 8; nt++)
                    qmma16(acc[mt][nt], a[cb][mt], b[cb][nt][0], b[cb][nt][1]);
        }

        if (++s == NSTAGE) s = 0;
        if (++ps == NSTAGE) ps = 0;
    }

    // epilogue: f16x2 acc -> bf16 PA (reg0 = row, reg1 = row+8)
#pragma unroll
    for (int mt = 0; mt < 2; mt++) {
#pragma unroll
        for (int nt = 0; nt < 8; nt++) {
            int row = m0 + wm * 32 + mt * 16 + (lane >> 2);
            int col = n0 + wn * 64 + nt * 8 + (lane & 3) * 2;
            float2 f0 = __half22float2(*reinterpret_cast<__half2*>(&acc[mt][nt][0]));
            float2 f1 = __half22float2(*reinterpret_cast<__half2*>(&acc[mt][nt][1]));
            *reinterpret_cast<__nv_bfloat162*>(&g_PA[(size_t)row * Q + col]) =
                __floats2bfloat162_rn(f0.x, f0.y);
            *reinterpret_cast<__nv_bfloat162*>(&g_PA[(size_t)(row + 8) * Q + col]) =
                __floats2bfloat162_rn(f1.x, f1.y);
        }
    }
}

// ---------------- kernel 4: per-edge gathered dot (bf16 x bf16) -------------
__global__ __launch_bounds__(256) void stage2_kernel(const int* __restrict__ esrc,
                                                     const int* __restrict__ edst,
                                                     const float* __restrict__ ew) {
    const int warp = threadIdx.x >> 5;
    const int lane = threadIdx.x & 31;
    const int eg = blockIdx.x * 8 + warp;
    const int b = eg >> 11;
    const int e = eg & (EDG - 1);

    const int src = esrc[b * EDG + e];
    const int dst = edst[b * EDG + e];
    const __nv_bfloat16* pa = &g_PA[(size_t)(b * NLOG + src) * Q];
    const __nv_bfloat16* pj = &g_Pb[(size_t)(b * NLOG + dst) * Q];

    float acc = 0.f;
    for (int q = lane * 8; q < Q; q += 256) {
        uint4 ua = *reinterpret_cast<const uint4*>(&pa[q]);
        uint4 ub = *reinterpret_cast<const uint4*>(&pj[q]);
        const __nv_bfloat162* ha = reinterpret_cast<const __nv_bfloat162*>(&ua);
        const __nv_bfloat162* hb = reinterpret_cast<const __nv_bfloat162*>(&ub);
#pragma unroll
        for (int j = 0; j < 4; j++) {
            float2 fa = __bfloat1622float2(ha[j]);
            float2 fb = __bfloat1622float2(hb[j]);
            acc += fa.x * fb.x + fa.y * fb.y;
        }
    }
#pragma unroll
    for (int o = 16; o; o >>= 1) acc += __shfl_xor_sync(0xffffffffu, acc, o);
    if (lane == 0) g_edot[eg] = acc * ew[b * EDG + e];
}

// ---------------- kernel 5: deterministic per-batch reduction ---------------
__global__ void reduce_batch_kernel(const float* __restrict__ ew) {
    __shared__ float sn[256], sd[256];
    const int b = blockIdx.x;
    const int t = threadIdx.x;
    float n = 0.f, d = 0.f;
    for (int e = t; e < EDG; e += 256) {
        n += g_edot[b * EDG + e];
        d += ew[b * EDG + e];
    }
    sn[t] = n; sd[t] = d;
    __syncthreads();
    for (int s = 128; s > 0; s >>= 1) {
        if (t < s) { sn[t] += sn[t + s]; sd[t] += sd[t + s]; }
        __syncthreads();
    }
    if (t == 0) { g_num[b] = sn[0]; g_den[b] = sd[0]; }
}

// ---------------- kernel 6: final loss --------------------------------------
__global__ void final_kernel(float* __restrict__ out) {
    const int t = threadIdx.x;
    float v = (t < BATCH) ? g_num[t] / fmaxf(g_den[t], 1e-8f) : 0.f;
#pragma unroll
    for (int o = 16; o; o >>= 1) v += __shfl_xor_sync(0xffffffffu, v, o);
    if (t == 0) out[0] = -v / (float)BATCH;
}

// ---------------- launch -----------------------------------------------------
extern "C" void kernel_launch(void* const* d_in, const int* in_sizes, int n_in,
                              void* d_out, int out_size) {
    const float* P   = (const float*)d_in[0];
    const int* dhw   = (const int*)  d_in[1];
    const int* esrc  = (const int*)  d_in[2];
    const int* edst  = (const int*)  d_in[3];
    const float* ew  = (const float*)d_in[4];
    float* out = (float*)d_out;

    static bool attr_done = false;
    if (!attr_done) {
        cudaFuncSetAttribute(gemm_fp8_kernel,
                             cudaFuncAttributeMaxDynamicSharedMemorySize, SMEM_SZ);
        attr_done = true;
    }

    conv_p_kernel<<<(MROWS * Q / 4) / 256, 256>>>(P);               // slot 1
    build_at_kernel<<<dim3(Q / 32, Q / 32), dim3(32, 8)>>>(dhw);    // slot 2
    init_kernel<<<1, 32>>>();                                       // slot 3
    gemm_fp8_kernel<<<dim3(Q / BN, MROWS / BM), 256, SMEM_SZ>>>();  // slot 4 (ncu)
    stage2_kernel<<<(BATCH * EDG) / 8, 256>>>(esrc, edst, ew);
    reduce_batch_kernel<<<BATCH, 256>>>(ew);
    final_kernel<<<1, 32>>>(out);
}

// round 17
// speedup vs baseline: 1.0779x; 1.0779x over previous
#include <cuda_runtime.h>
#include <cuda_bf16.h>
#include <cuda_fp8.h>
#include <cstdint>
#include <cstddef>

// ---------------- problem constants ----------------------------------------
#define BATCH 16
#define NLOG  512
#define Q     2048
#define EDG   2048
#define MROWS (BATCH * NLOG)   // 8192

// ---------------- FP8 GEMM tiling -------------------------------------------
#define BM 128
#define BN 128
#define BK 128                // e4m3 elements per chunk (128 bytes/row)
#define NKT (Q / BK)          // 16
#define LDR 144               // row stride bytes: 128 + 16 pad (conflict-free ldsm)
#define A_BYTES (BM * LDR)                 // 18432
#define STAGE_BYTES (2 * A_BYTES)          // 36864 (A + B)
#define NSTAGE 3
#define SMEM_SZ (NSTAGE * STAGE_BYTES)     // 110592 B

// ---------------- scratch (device globals; no allocation allowed) ----------
__device__ uint8_t       g_P8[(size_t)MROWS * Q];   // P e4m3 (16 MB, GEMM A + stage2 dst)
__device__ uint8_t       g_B8[(size_t)Q * Q];       // A_hw^T e4m3 [n][k] (4 MB, GEMM B)
__device__ __nv_bfloat16 g_PA[(size_t)MROWS * Q];   // P @ A_hw bf16 (32 MB)
__device__ float g_edot[BATCH * EDG];
__device__ float g_num[BATCH];
__device__ float g_den[BATCH];

// ---------------- PTX helpers ----------------------------------------------
__device__ __forceinline__ void cp16s(uint32_t s, const void* g) {
    asm volatile("cp.async.cg.shared.global [%0], [%1], 16;\n" :: "r"(s), "l"(g));
}
__device__ __forceinline__ void cp_commit() {
    asm volatile("cp.async.commit_group;\n" ::);
}
__device__ __forceinline__ void cp_wait1() {
    asm volatile("cp.async.wait_group 1;\n" ::);
}
__device__ __forceinline__ void cp_wait0() {
    asm volatile("cp.async.wait_group 0;\n" ::);
}
__device__ __forceinline__ void ldsm4(uint32_t& r0, uint32_t& r1, uint32_t& r2, uint32_t& r3,
                                      uint32_t a) {
    asm volatile("ldmatrix.sync.aligned.m8n8.x4.shared.b16 {%0,%1,%2,%3}, [%4];"
                 : "=r"(r0), "=r"(r1), "=r"(r2), "=r"(r3) : "r"(a));
}
// m16n8k32 e4m3 x e4m3 -> f32
__device__ __forceinline__ void qmma(float* c, const uint32_t* a, uint32_t b0, uint32_t b1) {
    asm volatile(
        "mma.sync.aligned.m16n8k32.row.col.f32.e4m3.e4m3.f32 "
        "{%0,%1,%2,%3}, {%4,%5,%6,%7}, {%8,%9}, {%0,%1,%2,%3};"
        : "+f"(c[0]), "+f"(c[1]), "+f"(c[2]), "+f"(c[3])
        : "r"(a[0]), "r"(a[1]), "r"(a[2]), "r"(a[3]), "r"(b0), "r"(b1));
}

// ---------------- kernel 1: P fp32 -> e4m3 only -----------------------------
__global__ void conv_p_kernel(const float* __restrict__ P) {
    int i = blockIdx.x * blockDim.x + threadIdx.x;     // 4 floats each
    float4 v = reinterpret_cast<const float4*>(P)[i];
    __nv_fp8x2_e4m3 lo(float2{v.x, v.y});   // low byte = v.x
    __nv_fp8x2_e4m3 hi(float2{v.z, v.w});
    uint32_t packed = (uint32_t)lo.__x | ((uint32_t)hi.__x << 16);
    reinterpret_cast<uint32_t*>(g_P8)[i] = packed;
}

// ---------------- kernel 2: g_B8[n][k] = (d_hw[k][n]==1) as e4m3, transpose -
__global__ void build_at_kernel(const int* __restrict__ dhw) {
    __shared__ uint8_t t[32][33];
    const int n0 = blockIdx.x * 32;
    const int k0 = blockIdx.y * 32;
    const int tx = threadIdx.x;       // 0..31
    const int ty = threadIdx.y;       // 0..7
#pragma unroll
    for (int j = 0; j < 4; j++) {
        int k = k0 + ty + j * 8;
        int d = dhw[(size_t)k * Q + n0 + tx];
        t[ty + j * 8][tx] = (d == 1) ? 0x38 : 0x00;   // e4m3 1.0 / 0.0
    }
    __syncthreads();
#pragma unroll
    for (int j = 0; j < 4; j++) {
        int n = n0 + ty + j * 8;
        g_B8[(size_t)n * Q + k0 + tx] = t[tx][ty + j * 8];
    }
}

// ---------------- kernel 2.5: tiny init (keeps GEMM in ncu slot 4) ----------
__global__ void init_kernel() {
    if (threadIdx.x < BATCH) { g_num[threadIdx.x] = 0.f; g_den[threadIdx.x] = 0.f; }
}

// ---------------- kernel 3: PA = P8 @ B8^T, FP8 mma.sync, 3-stage ring ------
// R11 champion: 256 threads, warptile 32x64, fp32 acc, hoisted addressing.
__global__ __launch_bounds__(256, 2) void gemm_fp8_kernel() {
    extern __shared__ uint8_t smem[];

    const int m0 = blockIdx.y * BM;
    const int n0 = blockIdx.x * BN;
    const int tid = threadIdx.x;
    const int lane = tid & 31;
    const int warp = tid >> 5;
    const int wm = warp & 3;   // warptile 32 along M
    const int wn = warp >> 2;  // warptile 64 along N

    const uint32_t smem_base = (uint32_t)__cvta_generic_to_shared(smem);

    // --- producer addressing (per-thread, hoisted) ---
    const int prow = tid >> 3;
    const int pcol = (tid & 7) * 16;
    const uint8_t* gA = g_P8 + (size_t)(m0 + prow) * Q + pcol;
    const uint8_t* gB = g_B8 + (size_t)(n0 + prow) * Q + pcol;
    const uint32_t soff = (uint32_t)(prow * LDR + pcol);

    // --- consumer addressing (per-thread, hoisted) ---
    const uint32_t aoff = (uint32_t)((wm * 32 + (lane & 15)) * LDR + (lane >> 4) * 16);
    const uint32_t boff = (uint32_t)A_BYTES +
        (uint32_t)((wn * 64 + ((lane >> 4) << 3) + (lane & 7)) * LDR +
                   ((lane >> 3) & 1) * 16);

    float acc[2][8][4];
#pragma unroll
    for (int mt = 0; mt < 2; mt++)
#pragma unroll
        for (int nt = 0; nt < 8; nt++)
#pragma unroll
            for (int j = 0; j < 4; j++) acc[mt][nt][j] = 0.f;

    // one stage fill: 4 A slots + 4 B slots, immediates only
    auto fill = [&](uint32_t sb) {
#pragma unroll
        for (int i = 0; i < 4; i++) {
            cp16s(sb + soff + (uint32_t)(i * 32 * LDR), gA + (size_t)i * 32 * Q);
            cp16s(sb + soff + (uint32_t)(i * 32 * LDR) + A_BYTES, gB + (size_t)i * 32 * Q);
        }
        cp_commit();
        gA += BK; gB += BK;
    };

    // prologue: stages 0,1
    fill(smem_base);
    fill(smem_base + STAGE_BYTES);

    int s = 0, ps = 2;   // compute stage, prefetch stage
    for (int kt = 0; kt < NKT; kt++) {
        if (kt + 1 < NKT) cp_wait1(); else cp_wait0();
        __syncthreads();

        const uint32_t Ab = smem_base + (uint32_t)s * STAGE_BYTES + aoff;
        const uint32_t Bb = smem_base + (uint32_t)s * STAGE_BYTES + boff;

#pragma unroll
        for (int ks = 0; ks < 4; ks++) {           // four k32 steps per BK=128
            uint32_t a[2][4];
#pragma unroll
            for (int mt = 0; mt < 2; mt++)
                ldsm4(a[mt][0], a[mt][1], a[mt][2], a[mt][3],
                      Ab + (uint32_t)(mt * 16 * LDR + ks * 32));
            uint32_t b[8][2];
#pragma unroll
            for (int nt2 = 0; nt2 < 4; nt2++)
                ldsm4(b[2 * nt2][0], b[2 * nt2][1], b[2 * nt2 + 1][0], b[2 * nt2 + 1][1],
                      Bb + (uint32_t)(nt2 * 16 * LDR + ks * 32));
#pragma unroll
            for (int mt = 0; mt < 2; mt++)
#pragma unroll
                for (int nt = 0; nt < 8; nt++)
                    qmma(acc[mt][nt], a[mt], b[nt][0], b[nt][1]);
        }

        if (kt + 2 < NKT)                          // prefetch stage kt+2
            fill(smem_base + (uint32_t)ps * STAGE_BYTES);
        if (++s == NSTAGE) s = 0;
        if (++ps == NSTAGE) ps = 0;
    }

    // epilogue: fp32 acc -> bf16 PA (standard mma C fragment mapping)
#pragma unroll
    for (int mt = 0; mt < 2; mt++) {
#pragma unroll
        for (int nt = 0; nt < 8; nt++) {
            int row = m0 + wm * 32 + mt * 16 + (lane >> 2);
            int col = n0 + wn * 64 + nt * 8 + (lane & 3) * 2;
            *reinterpret_cast<__nv_bfloat162*>(&g_PA[(size_t)row * Q + col]) =
                __floats2bfloat162_rn(acc[mt][nt][0], acc[mt][nt][1]);
            *reinterpret_cast<__nv_bfloat162*>(&g_PA[(size_t)(row + 8) * Q + col]) =
                __floats2bfloat162_rn(acc[mt][nt][2], acc[mt][nt][3]);
        }
    }
}

// ---------------- kernel 4: per-edge gathered dot (bf16 PA x fp8 dst) -------
__global__ __launch_bounds__(256) void stage2_kernel(const int* __restrict__ esrc,
                                                     const int* __restrict__ edst,
                                                     const float* __restrict__ ew) {
    const int warp = threadIdx.x >> 5;
    const int lane = threadIdx.x & 31;
    const int eg = blockIdx.x * 8 + warp;
    const int b = eg >> 11;
    const int e = eg & (EDG - 1);

    const int src = esrc[b * EDG + e];
    const int dst = edst[b * EDG + e];
    const __nv_bfloat16* pa = &g_PA[(size_t)(b * NLOG + src) * Q];
    const uint8_t* pj = &g_P8[(size_t)(b * NLOG + dst) * Q];

    float acc = 0.f;
    for (int q = lane * 8; q < Q; q += 256) {
        uint4 ua = *reinterpret_cast<const uint4*>(&pa[q]);   // 8 bf16
        uint2 ub = *reinterpret_cast<const uint2*>(&pj[q]);   // 8 e4m3
        const __nv_bfloat162* ha = reinterpret_cast<const __nv_bfloat162*>(&ua);
        const __nv_fp8x2_e4m3* hb = reinterpret_cast<const __nv_fp8x2_e4m3*>(&ub);
#pragma unroll
        for (int j = 0; j < 4; j++) {
            float2 fa = __bfloat1622float2(ha[j]);
            float2 fb = (float2)hb[j];
            acc += fa.x * fb.x + fa.y * fb.y;
        }
    }
#pragma unroll
    for (int o = 16; o; o >>= 1) acc += __shfl_xor_sync(0xffffffffu, acc, o);
    if (lane == 0) g_edot[eg] = acc * ew[b * EDG + e];
}

// ---------------- kernel 5: deterministic per-batch reduction ---------------
__global__ void reduce_batch_kernel(const float* __restrict__ ew) {
    __shared__ float sn[256], sd[256];
    const int b = blockIdx.x;
    const int t = threadIdx.x;
    float n = 0.f, d = 0.f;
    for (int e = t; e < EDG; e += 256) {
        n += g_edot[b * EDG + e];
        d += ew[b * EDG + e];
    }
    sn[t] = n; sd[t] = d;
    __syncthreads();
    for (int s = 128; s > 0; s >>= 1) {
        if (t < s) { sn[t] += sn[t + s]; sd[t] += sd[t + s]; }
        __syncthreads();
    }
    if (t == 0) { g_num[b] = sn[0]; g_den[b] = sd[0]; }
}

// ---------------- kernel 6: final loss --------------------------------------
__global__ void final_kernel(float* __restrict__ out) {
    const int t = threadIdx.x;
    float v = (t < BATCH) ? g_num[t] / fmaxf(g_den[t], 1e-8f) : 0.f;
#pragma unroll
    for (int o = 16; o; o >>= 1) v += __shfl_xor_sync(0xffffffffu, v, o);
    if (t == 0) out[0] = -v / (float)BATCH;
}

// ---------------- launch -----------------------------------------------------
extern "C" void kernel_launch(void* const* d_in, const int* in_sizes, int n_in,
                              void* d_out, int out_size) {
    const float* P   = (const float*)d_in[0];
    const int* dhw   = (const int*)  d_in[1];
    const int* esrc  = (const int*)  d_in[2];
    const int* edst  = (const int*)  d_in[3];
    const float* ew  = (const float*)d_in[4];
    float* out = (float*)d_out;

    static bool attr_done = false;
    if (!attr_done) {
        cudaFuncSetAttribute(gemm_fp8_kernel,
                             cudaFuncAttributeMaxDynamicSharedMemorySize, SMEM_SZ);
        attr_done = true;
    }

    conv_p_kernel<<<(MROWS * Q / 4) / 256, 256>>>(P);               // slot 1
    build_at_kernel<<<dim3(Q / 32, Q / 32), dim3(32, 8)>>>(dhw);    // slot 2
    init_kernel<<<1, 32>>>();                                       // slot 3
    gemm_fp8_kernel<<<dim3(Q / BN, MROWS / BM), 256, SMEM_SZ>>>();  // slot 4 (ncu)
    stage2_kernel<<<(BATCH * EDG) / 8, 256>>>(esrc, edst, ew);
    reduce_batch_kernel<<<BATCH, 256>>>(ew);
    final_kernel<<<1, 32>>>(out);
}